// round 1
// baseline (speedup 1.0000x reference)
#include <cuda_runtime.h>
#include <cuda_bf16.h>
#include <cstdint>
#include <cstdio>

// Problem constants
#define TT 40
#define NB 64            // batch
#define EE 512           // embed
#define HENC 256         // encoder hidden per direction
#define HDEC 512         // decoder hidden
#define TB (TT*NB)       // 2560 rows
#define VT 32000

// ---------------------------------------------------------------------------
// Scratch (static device globals; no allocation allowed)
// ---------------------------------------------------------------------------
__device__ float g_bufA[TB * EE];          // 5.24 MB  ping
__device__ float g_bufB[TB * EE];          // 5.24 MB  pong
__device__ float g_xg[TB * 2048];          // 21 MB    precomputed input gates
__device__ float g_h0[2 * NB * 512];       // h ping (enc: [dir][b][256]; dec: [b][512])
__device__ float g_h1[2 * NB * 512];       // h pong
__device__ float g_cst[2 * NB * 512];      // c state (owner-only access, no ping-pong needed)
__device__ float g_hfin[2 * NB * 512];     // encoder final h per layer (concat fwd|bwd)
__device__ float g_cfin[2 * NB * 512];

// ---------------------------------------------------------------------------
// Embedding gather: out[i,:] = emb[tok[i],:]   (E=512 -> 128 float4)
// ---------------------------------------------------------------------------
__global__ __launch_bounds__(128) void k_embed(const int* __restrict__ tok,
                                               const float* __restrict__ emb,
                                               float* __restrict__ out) {
    int i = blockIdx.x;
    int t = tok[i];
    const float4* s = (const float4*)(emb + (size_t)t * EE);
    float4* d = (float4*)(out + (size_t)i * EE);
    d[threadIdx.x] = s[threadIdx.x];
}

// ---------------------------------------------------------------------------
// State init: h/c <- src (or zero if src null)
// ---------------------------------------------------------------------------
__global__ void k_state(float* __restrict__ h, float* __restrict__ c,
                        const float* __restrict__ hs, const float* __restrict__ cs,
                        int n) {
    int i = blockIdx.x * blockDim.x + threadIdx.x;
    if (i < n) {
        h[i] = hs ? hs[i] : 0.0f;
        c[i] = cs ? cs[i] : 0.0f;
    }
}

// ---------------------------------------------------------------------------
// fp32 GEMM:  C[M,N] = A[M,K] * W[N,K]^T + bias[N]
// 128x128 block tile, BK=8, 256 threads, 8x8 micro-tile.
// Requires M%128==0, N%128==0, K%8==0 (true here: M=2560, N in {2048,32000}, K=512)
// ---------------------------------------------------------------------------
__global__ __launch_bounds__(256) void k_gemm(const float* __restrict__ A,
                                              const float* __restrict__ W,
                                              const float* __restrict__ bias,
                                              float* __restrict__ C,
                                              int M, int N, int K) {
    __shared__ float As[8][128];
    __shared__ float Ws[8][128];
    const int bm = blockIdx.y * 128;
    const int bn = blockIdx.x * 128;
    const int tid = threadIdx.x;
    const int lr = tid >> 1;           // 0..127 load row
    const int lc = (tid & 1) << 2;     // 0 or 4 load k-offset
    const int tx = tid & 15;           // 0..15
    const int ty = tid >> 4;           // 0..15

    const float* Ap = A + (size_t)(bm + lr) * K + lc;
    const float* Wp = W + (size_t)(bn + lr) * K + lc;

    float acc[8][8];
#pragma unroll
    for (int i = 0; i < 8; i++)
#pragma unroll
        for (int j = 0; j < 8; j++) acc[i][j] = 0.0f;

    for (int k0 = 0; k0 < K; k0 += 8) {
        float4 a = *(const float4*)(Ap + k0);
        float4 w = *(const float4*)(Wp + k0);
        __syncthreads();
        As[lc + 0][lr] = a.x; As[lc + 1][lr] = a.y;
        As[lc + 2][lr] = a.z; As[lc + 3][lr] = a.w;
        Ws[lc + 0][lr] = w.x; Ws[lc + 1][lr] = w.y;
        Ws[lc + 2][lr] = w.z; Ws[lc + 3][lr] = w.w;
        __syncthreads();
#pragma unroll
        for (int kk = 0; kk < 8; kk++) {
            float ar[8], wr[8];
            float4 a0 = *(const float4*)&As[kk][ty * 4];
            float4 a1 = *(const float4*)&As[kk][64 + ty * 4];
            float4 w0 = *(const float4*)&Ws[kk][tx * 4];
            float4 w1 = *(const float4*)&Ws[kk][64 + tx * 4];
            ar[0]=a0.x; ar[1]=a0.y; ar[2]=a0.z; ar[3]=a0.w;
            ar[4]=a1.x; ar[5]=a1.y; ar[6]=a1.z; ar[7]=a1.w;
            wr[0]=w0.x; wr[1]=w0.y; wr[2]=w0.z; wr[3]=w0.w;
            wr[4]=w1.x; wr[5]=w1.y; wr[6]=w1.z; wr[7]=w1.w;
#pragma unroll
            for (int i = 0; i < 8; i++)
#pragma unroll
                for (int j = 0; j < 8; j++)
                    acc[i][j] = fmaf(ar[i], wr[j], acc[i][j]);
        }
    }

    float4 b0 = *(const float4*)(bias + bn + tx * 4);
    float4 b1 = *(const float4*)(bias + bn + 64 + tx * 4);
#pragma unroll
    for (int i = 0; i < 8; i++) {
        int row = bm + ((i < 4) ? (ty * 4 + i) : (64 + ty * 4 + (i - 4)));
        float* Cr = C + (size_t)row * N + bn;
        float4 v0, v1;
        v0.x = acc[i][0] + b0.x; v0.y = acc[i][1] + b0.y;
        v0.z = acc[i][2] + b0.z; v0.w = acc[i][3] + b0.w;
        v1.x = acc[i][4] + b1.x; v1.y = acc[i][5] + b1.y;
        v1.z = acc[i][6] + b1.z; v1.w = acc[i][7] + b1.w;
        *(float4*)(Cr + tx * 4) = v0;
        *(float4*)(Cr + 64 + tx * 4) = v1;
    }
}

// ---------------------------------------------------------------------------
// LSTM recurrent step.
// HC = hidden per direction (256 enc, 512 dec), NDIR = 2 (enc) or 1 (dec).
// Grid: (HC/4, NDIR), 128 threads. Each block owns 4 hidden units for one
// direction. Thread (b = tid&31, ul = tid>>5) computes all 4 gates for batch
// rows b and b+32 of unit u0+ul, then does the c/h update inline.
// h is ping-pong buffered (hin read-all / hout write-disjoint across blocks).
// Gate order (PyTorch): i, f, g, o in chunks of HC.
// ---------------------------------------------------------------------------
template <int HC, int NDIR>
__global__ __launch_bounds__(128) void k_lstm_step(
    const float* __restrict__ xg,    // [T*64, NDIR*4*HC]
    const float* __restrict__ Whh,   // [NDIR*4*HC, HC]
    const float* __restrict__ bhh,   // [NDIR*4*HC]
    const float* __restrict__ hin,   // [NDIR*64*HC]
    float* __restrict__ hout,
    float* __restrict__ c,           // [NDIR*64*HC]
    float* __restrict__ y,           // [T*64, NDIR*HC]
    float* __restrict__ hfin, float* __restrict__ cfin,  // [64, NDIR*HC] (enc only)
    int t, int writeFin) {
    constexpr int K4 = HC / 4;
    const int dir = (NDIR == 2) ? blockIdx.y : 0;
    const int td = dir ? (TT - 1 - t) : t;
    const int u0 = blockIdx.x * 4;
    const int tid = threadIdx.x;

    extern __shared__ float4 sm4[];
    float4* hs = sm4;             // [K4][64]  h transposed (k-major)
    float4* ws = sm4 + K4 * 64;   // [16][K4]  this block's 16 Whh rows

    const float* hdin = hin + dir * NB * HC;
    float* hdout = hout + dir * NB * HC;
    float* cdir = c + dir * NB * HC;
    const float* wbase = Whh + (size_t)dir * 4 * HC * HC;

    for (int i = tid; i < NB * K4; i += 128) {
        int b = i & 63, k4 = i >> 6;
        hs[k4 * 64 + b] = ((const float4*)(hdin + b * HC))[k4];
    }
    for (int i = tid; i < 16 * K4; i += 128) {
        int r = i / K4, k4 = i - r * K4;
        int g = r >> 2, ul = r & 3;
        ws[i] = ((const float4*)(wbase + (size_t)(g * HC + u0 + ul) * HC))[k4];
    }
    __syncthreads();

    const int b = tid & 31;
    const int ul = tid >> 5;
    float a0[4] = {0, 0, 0, 0}, a1[4] = {0, 0, 0, 0};

#pragma unroll 4
    for (int k4 = 0; k4 < K4; k4++) {
        float4 h0 = hs[k4 * 64 + b];
        float4 h1 = hs[k4 * 64 + b + 32];
#pragma unroll
        for (int g = 0; g < 4; g++) {
            float4 wv = ws[(g * 4 + ul) * K4 + k4];
            a0[g] += h0.x * wv.x + h0.y * wv.y + h0.z * wv.z + h0.w * wv.w;
            a1[g] += h1.x * wv.x + h1.y * wv.y + h1.z * wv.z + h1.w * wv.w;
        }
    }

    const int u = u0 + ul;
    const int XW = NDIR * 4 * HC;
    const int xb = dir * 4 * HC;

#define LSTM_UPDATE(A0, A1, A2, A3, BG)                                          \
    {                                                                            \
        const int bg = (BG);                                                     \
        const size_t xr = (size_t)(td * NB + bg) * XW + xb + u;                  \
        float vi = (A0) + xg[xr] + bhh[xb + u];                                  \
        float vf = (A1) + xg[xr + HC] + bhh[xb + HC + u];                        \
        float vg = (A2) + xg[xr + 2 * HC] + bhh[xb + 2 * HC + u];                \
        float vo = (A3) + xg[xr + 3 * HC] + bhh[xb + 3 * HC + u];                \
        float si = 1.0f / (1.0f + expf(-vi));                                    \
        float sf = 1.0f / (1.0f + expf(-vf));                                    \
        float so = 1.0f / (1.0f + expf(-vo));                                    \
        float cold = cdir[bg * HC + u];                                          \
        float cn = sf * cold + si * tanhf(vg);                                   \
        float hn = so * tanhf(cn);                                               \
        cdir[bg * HC + u] = cn;                                                  \
        hdout[bg * HC + u] = hn;                                                 \
        y[(size_t)(td * NB + bg) * (NDIR * HC) + dir * HC + u] = hn;             \
        if (writeFin) {                                                          \
            hfin[bg * (NDIR * HC) + dir * HC + u] = hn;                          \
            cfin[bg * (NDIR * HC) + dir * HC + u] = cn;                          \
        }                                                                        \
    }

    LSTM_UPDATE(a0[0], a0[1], a0[2], a0[3], b);
    LSTM_UPDATE(a1[0], a1[1], a1[2], a1[3], b + 32);
#undef LSTM_UPDATE
}

// ---------------------------------------------------------------------------
// Host launcher
// ---------------------------------------------------------------------------
extern "C" void kernel_launch(void* const* d_in, const int* in_sizes, int n_in,
                              void* d_out, int out_size) {
    const int* src = (const int*)d_in[0];
    const int* tgt = (const int*)d_in[1];
    const float* semb = (const float*)d_in[2];
    const float* temb = (const float*)d_in[3];
    const float* eWih = (const float*)d_in[4];   // [2,2,1024,512]
    const float* eWhh = (const float*)d_in[5];   // [2,2,1024,256]
    const float* ebih = (const float*)d_in[6];   // [2,2,1024]
    const float* ebhh = (const float*)d_in[7];   // [2,2,1024]
    const float* dWih = (const float*)d_in[8];   // [2,2048,512]
    const float* dWhh = (const float*)d_in[9];   // [2,2048,512]
    const float* dbih = (const float*)d_in[10];  // [2,2048]
    const float* dbhh = (const float*)d_in[11];  // [2,2048]
    const float* linW = (const float*)d_in[12];  // [32000,512]
    const float* linb = (const float*)d_in[13];  // [32000]
    float* out = (float*)d_out;

    float *bufA, *bufB, *xg, *h0, *h1, *cs, *hf, *cf;
    cudaGetSymbolAddress((void**)&bufA, g_bufA);
    cudaGetSymbolAddress((void**)&bufB, g_bufB);
    cudaGetSymbolAddress((void**)&xg, g_xg);
    cudaGetSymbolAddress((void**)&h0, g_h0);
    cudaGetSymbolAddress((void**)&h1, g_h1);
    cudaGetSymbolAddress((void**)&cs, g_cst);
    cudaGetSymbolAddress((void**)&hf, g_hfin);
    cudaGetSymbolAddress((void**)&cf, g_cfin);

    const int SMEM_ENC = (64 * 64 + 16 * 64) * 16;    // 81920 B
    const int SMEM_DEC = (64 * 128 + 16 * 128) * 16;  // 163840 B
    cudaFuncSetAttribute((const void*)k_lstm_step<HENC, 2>,
                         cudaFuncAttributeMaxDynamicSharedMemorySize, SMEM_ENC);
    cudaFuncSetAttribute((const void*)k_lstm_step<HDEC, 1>,
                         cudaFuncAttributeMaxDynamicSharedMemorySize, SMEM_DEC);

    // ---- Encoder ----
    k_embed<<<TB, 128>>>(src, semb, bufA);
    for (int l = 0; l < 2; l++) {
        const float* xin = (l == 0) ? bufA : bufB;
        float* yout = (l == 0) ? bufB : bufA;
        // xg[2560,2048] = x @ Wih[l]^T + bih[l]   (both directions fused)
        k_gemm<<<dim3(16, 20), 256>>>(xin, eWih + (size_t)l * 2048 * 512,
                                      ebih + l * 2048, xg, TB, 2048, 512);
        k_state<<<128, 256>>>(h0, cs, nullptr, nullptr, 2 * NB * HENC);
        for (int t = 0; t < TT; t++) {
            float* hin = (t & 1) ? h1 : h0;
            float* hout = (t & 1) ? h0 : h1;
            k_lstm_step<HENC, 2><<<dim3(HENC / 4, 2), 128, SMEM_ENC>>>(
                xg, eWhh + (size_t)l * 2 * 1024 * 256, ebhh + l * 2048,
                hin, hout, cs, yout,
                hf + l * NB * 512, cf + l * NB * 512, t, (t == TT - 1) ? 1 : 0);
        }
    }

    // ---- Decoder ----
    k_embed<<<TB, 128>>>(tgt, temb, bufA);
    for (int l = 0; l < 2; l++) {
        const float* yin = (l == 0) ? bufA : bufB;
        float* yout = (l == 0) ? bufB : bufA;
        k_gemm<<<dim3(16, 20), 256>>>(yin, dWih + (size_t)l * 2048 * 512,
                                      dbih + l * 2048, xg, TB, 2048, 512);
        k_state<<<128, 256>>>(h0, cs, hf + l * NB * 512, cf + l * NB * 512,
                              NB * HDEC);
        for (int t = 0; t < TT; t++) {
            float* hin = (t & 1) ? h1 : h0;
            float* hout = (t & 1) ? h0 : h1;
            k_lstm_step<HDEC, 1><<<dim3(HDEC / 4, 1), 128, SMEM_DEC>>>(
                xg, dWhh + (size_t)l * 2048 * 512, dbhh + l * 2048,
                hin, hout, cs, yout, nullptr, nullptr, t, 0);
        }
    }

    // ---- Output projection: logits[2560,32000] ----
    k_gemm<<<dim3(VT / 128, TB / 128), 256>>>(bufA, linW, linb, out, TB, VT, 512);
}

// round 4
// speedup vs baseline: 1.1389x; 1.1389x over previous
#include <cuda_runtime.h>
#include <cuda_bf16.h>
#include <cstdint>

// Problem constants
#define TT 40
#define NB 64            // batch
#define EE 512           // embed
#define HENC 256         // encoder hidden per direction
#define HDEC 512         // decoder hidden
#define TB (TT*NB)       // 2560 rows
#define VT 32000

// ---------------------------------------------------------------------------
// Scratch (static device globals; no allocation allowed)
// ---------------------------------------------------------------------------
__device__ float g_bufA[TB * EE];          // 5.24 MB  ping
__device__ float g_bufB[TB * EE];          // 5.24 MB  pong
__device__ float g_xgT[2048 * TB];         // 21 MB    input gates, TRANSPOSED [gate][row]
__device__ float g_hA[32768];              // h ping, transposed layout (128 KB)
__device__ float g_hB[32768];              // h pong
__device__ float g_cst[65536];             // c state, [dir*HC+u][b] layout
__device__ float g_hfin[2 * NB * 512];     // encoder final h per layer (concat f|b)
__device__ float g_cfin[2 * NB * 512];

// ---------------------------------------------------------------------------
// f32x2 packed-math helpers (Blackwell FFMA2: 2x fp32 FMA throughput,
// only reachable via PTX fma.rn.f32x2; bit-exact IEEE fp32 per lane)
// ---------------------------------------------------------------------------
typedef unsigned long long ull;

__device__ __forceinline__ ull f2u(float x, float y) {
    ull r; asm("mov.b64 %0, {%1, %2};" : "=l"(r) : "f"(x), "f"(y)); return r;
}
__device__ __forceinline__ ull ffma2(ull a, ull b, ull c) {
    ull d; asm("fma.rn.f32x2 %0, %1, %2, %3;" : "=l"(d) : "l"(a), "l"(b), "l"(c)); return d;
}
__device__ __forceinline__ float2 u2f(ull v) {
    float2 r; asm("mov.b64 {%0, %1}, %2;" : "=f"(r.x), "=f"(r.y) : "l"(v)); return r;
}
__device__ __forceinline__ float sigf(float x) {
    return 1.0f / (1.0f + __expf(-x));
}

// ---------------------------------------------------------------------------
// Embedding gather
// ---------------------------------------------------------------------------
__global__ __launch_bounds__(128) void k_embed(const int* __restrict__ tok,
                                               const float* __restrict__ emb,
                                               float* __restrict__ out) {
    int i = blockIdx.x;
    int t = tok[i];
    const float4* s = (const float4*)(emb + (size_t)t * EE);
    float4* d = (float4*)(out + (size_t)i * EE);
    d[threadIdx.x] = s[threadIdx.x];
}

// ---------------------------------------------------------------------------
// Init: encoder h/c zeros ; decoder h/c from encoder finals.
// h layout: hT[k4][b] packs h[b][4k4..4k4+3] as float4 (per-dir slab for enc)
// c layout: c[(dir*HC+u)*64 + b]
// ---------------------------------------------------------------------------
__global__ void k_init_enc(float* __restrict__ hA, float* __restrict__ cst) {
    int i = blockIdx.x * blockDim.x + threadIdx.x;
    for (int j = i; j < 32768; j += gridDim.x * blockDim.x) hA[j] = 0.0f;
    for (int j = i; j < 65536; j += gridDim.x * blockDim.x) cst[j] = 0.0f;
}

__global__ void k_init_dec(float* __restrict__ hA, float* __restrict__ cst,
                           const float* __restrict__ hf, const float* __restrict__ cf) {
    int i = blockIdx.x * blockDim.x + threadIdx.x;
    for (int j = i; j < 32768; j += gridDim.x * blockDim.x) {
        int k4 = j >> 8;          // 0..127
        int rem = j & 255;
        int bb = rem >> 2;        // 0..63
        int comp = rem & 3;
        hA[j] = hf[bb * 512 + k4 * 4 + comp];
    }
    for (int j = i; j < 32768; j += gridDim.x * blockDim.x) {
        int u = j >> 6;           // 0..511
        int bb = j & 63;
        cst[j] = cf[bb * 512 + u];
    }
}

// ---------------------------------------------------------------------------
// LSTM single step. No smem, no inter-block sync. All operands stream from
// L1/L2: h via plain coalesced float4 loads (transposed layout; safe because
// L1 is flushed at launch boundaries and hin/hout ping-pong), Whh rows via
// __ldg (warp-uniform), xg via transposed coalesced loads, c via [u][b].
// Grid: enc (HC/4, 2), dec (HC/4, 1); 128 threads.
// Thread (b=tid&31, ul=tid>>5): all 4 gates of unit u0+ul for batch b, b+32.
// ---------------------------------------------------------------------------
template <int HC, int NDIR>
__global__ __launch_bounds__(128) void k_step(
    const float* __restrict__ xgT,   // [NDIR*4*HC][TB]
    const float* __restrict__ Whh,   // [NDIR*4*HC, HC]
    const float* __restrict__ bhh,   // [NDIR*4*HC]
    const float4* __restrict__ hin,  // transposed, per-dir slabs
    float* __restrict__ hout,
    float* __restrict__ cst,         // [dir*HC+u][64]
    float* __restrict__ y,           // [T*64, NDIR*HC]
    float* __restrict__ hfin, float* __restrict__ cfin,  // enc finals
    int t)
{
    constexpr int K4 = HC / 4;
    const int dir = (NDIR == 2) ? blockIdx.y : 0;
    const int td = dir ? (TT - 1 - t) : t;
    const int u0 = blockIdx.x * 4;
    const int tid = threadIdx.x;
    const int b = tid & 31;
    const int ul = tid >> 5;
    const int u = u0 + ul;
    const int xb = dir * 4 * HC;

    const float4* hrow = hin + dir * (K4 * 64);           // this dir's slab
    const float* wbase = Whh + (size_t)dir * 4 * HC * HC;
    const float4* w0 = (const float4*)(wbase + (size_t)(0 * HC + u) * HC);
    const float4* w1 = (const float4*)(wbase + (size_t)(1 * HC + u) * HC);
    const float4* w2 = (const float4*)(wbase + (size_t)(2 * HC + u) * HC);
    const float4* w3 = (const float4*)(wbase + (size_t)(3 * HC + u) * HC);

    ull a0g0 = 0, a0g1 = 0, a0g2 = 0, a0g3 = 0;   // batch b
    ull a1g0 = 0, a1g1 = 0, a1g2 = 0, a1g3 = 0;   // batch b+32

#pragma unroll 8
    for (int k4 = 0; k4 < K4; k4++) {
        float4 h0 = hrow[k4 * 64 + b];
        float4 h1 = hrow[k4 * 64 + b + 32];
        float4 wv0 = __ldg(w0 + k4);
        float4 wv1 = __ldg(w1 + k4);
        float4 wv2 = __ldg(w2 + k4);
        float4 wv3 = __ldg(w3 + k4);
        ull h0a = f2u(h0.x, h0.y), h0b = f2u(h0.z, h0.w);
        ull h1a = f2u(h1.x, h1.y), h1b = f2u(h1.z, h1.w);
        ull w0a = f2u(wv0.x, wv0.y), w0b = f2u(wv0.z, wv0.w);
        ull w1a = f2u(wv1.x, wv1.y), w1b = f2u(wv1.z, wv1.w);
        ull w2a = f2u(wv2.x, wv2.y), w2b = f2u(wv2.z, wv2.w);
        ull w3a = f2u(wv3.x, wv3.y), w3b = f2u(wv3.z, wv3.w);
        a0g0 = ffma2(h0a, w0a, a0g0); a0g0 = ffma2(h0b, w0b, a0g0);
        a0g1 = ffma2(h0a, w1a, a0g1); a0g1 = ffma2(h0b, w1b, a0g1);
        a0g2 = ffma2(h0a, w2a, a0g2); a0g2 = ffma2(h0b, w2b, a0g2);
        a0g3 = ffma2(h0a, w3a, a0g3); a0g3 = ffma2(h0b, w3b, a0g3);
        a1g0 = ffma2(h1a, w0a, a1g0); a1g0 = ffma2(h1b, w0b, a1g0);
        a1g1 = ffma2(h1a, w1a, a1g1); a1g1 = ffma2(h1b, w1b, a1g1);
        a1g2 = ffma2(h1a, w2a, a1g2); a1g2 = ffma2(h1b, w2b, a1g2);
        a1g3 = ffma2(h1a, w3a, a1g3); a1g3 = ffma2(h1b, w3b, a1g3);
    }

    // biases + gate inputs (xgT coalesced: lane index = batch)
    const float bh0 = __ldg(bhh + xb + 0 * HC + u);
    const float bh1 = __ldg(bhh + xb + 1 * HC + u);
    const float bh2 = __ldg(bhh + xb + 2 * HC + u);
    const float bh3 = __ldg(bhh + xb + 3 * HC + u);
    const size_t rowoff = (size_t)td * NB;
    const float* xg0 = xgT + (size_t)(xb + 0 * HC + u) * TB + rowoff;
    const float* xg1 = xgT + (size_t)(xb + 1 * HC + u) * TB + rowoff;
    const float* xg2 = xgT + (size_t)(xb + 2 * HC + u) * TB + rowoff;
    const float* xg3 = xgT + (size_t)(xb + 3 * HC + u) * TB + rowoff;

    float* hd = hout + dir * (K4 * 256);
    const int k4u = u >> 2;
    const int comp = u & 3;
    float* crow = cst + (size_t)(dir * HC + u) * 64;

#pragma unroll
    for (int half = 0; half < 2; half++) {
        const int bg = b + half * 32;
        float2 s0 = u2f(half ? a1g0 : a0g0);
        float2 s1 = u2f(half ? a1g1 : a0g1);
        float2 s2 = u2f(half ? a1g2 : a0g2);
        float2 s3 = u2f(half ? a1g3 : a0g3);
        float vi = s0.x + s0.y + xg0[bg] + bh0;
        float vf = s1.x + s1.y + xg1[bg] + bh1;
        float vg = s2.x + s2.y + xg2[bg] + bh2;
        float vo = s3.x + s3.y + xg3[bg] + bh3;
        float cn = sigf(vf) * crow[bg] + sigf(vi) * tanhf(vg);
        float hn = sigf(vo) * tanhf(cn);
        crow[bg] = cn;
        hd[k4u * 256 + bg * 4 + comp] = hn;
        y[(size_t)(td * NB + bg) * (NDIR * HC) + dir * HC + u] = hn;
        if (NDIR == 2 && t == TT - 1) {
            hfin[bg * (2 * HC) + dir * HC + u] = hn;
            cfin[bg * (2 * HC) + dir * HC + u] = cn;
        }
    }
}

// ---------------------------------------------------------------------------
// Shared GEMM core: acc[8][4] (f32x2) of C[M,N] = A[M,K]*W[N,K]^T
// 128x128 tile, BK=8, 256 threads, 8x8 micro-tile, register prefetch.
// ---------------------------------------------------------------------------
struct GemmAcc { ull a[8][4]; };

__device__ __forceinline__ void gemm_core(const float* __restrict__ A,
                                          const float* __restrict__ W,
                                          int K, int bm, int bn,
                                          int tid, GemmAcc& g) {
    __shared__ float As[8][128];
    __shared__ float Ws[8][128];
    const int lr = tid >> 1;
    const int lc = (tid & 1) << 2;
    const int tx = tid & 15;
    const int ty = tid >> 4;

    const float* Ap = A + (size_t)(bm + lr) * K + lc;
    const float* Wp = W + (size_t)(bn + lr) * K + lc;

#pragma unroll
    for (int i = 0; i < 8; i++)
#pragma unroll
        for (int j = 0; j < 4; j++) g.a[i][j] = 0;

    float4 a = *(const float4*)Ap;
    float4 w = *(const float4*)Wp;

    for (int k0 = 0; k0 < K; k0 += 8) {
        __syncthreads();
        As[lc + 0][lr] = a.x; As[lc + 1][lr] = a.y;
        As[lc + 2][lr] = a.z; As[lc + 3][lr] = a.w;
        Ws[lc + 0][lr] = w.x; Ws[lc + 1][lr] = w.y;
        Ws[lc + 2][lr] = w.z; Ws[lc + 3][lr] = w.w;
        __syncthreads();
        if (k0 + 8 < K) {
            a = *(const float4*)(Ap + k0 + 8);
            w = *(const float4*)(Wp + k0 + 8);
        }
#pragma unroll
        for (int kk = 0; kk < 8; kk++) {
            float4 a0 = *(const float4*)&As[kk][ty * 4];
            float4 a1 = *(const float4*)&As[kk][64 + ty * 4];
            ulonglong2 w0 = *(const ulonglong2*)&Ws[kk][tx * 4];
            ulonglong2 w1 = *(const ulonglong2*)&Ws[kk][64 + tx * 4];
            ull ab[8];
            ab[0] = f2u(a0.x, a0.x); ab[1] = f2u(a0.y, a0.y);
            ab[2] = f2u(a0.z, a0.z); ab[3] = f2u(a0.w, a0.w);
            ab[4] = f2u(a1.x, a1.x); ab[5] = f2u(a1.y, a1.y);
            ab[6] = f2u(a1.z, a1.z); ab[7] = f2u(a1.w, a1.w);
#pragma unroll
            for (int i = 0; i < 8; i++) {
                g.a[i][0] = ffma2(ab[i], w0.x, g.a[i][0]);
                g.a[i][1] = ffma2(ab[i], w0.y, g.a[i][1]);
                g.a[i][2] = ffma2(ab[i], w1.x, g.a[i][2]);
                g.a[i][3] = ffma2(ab[i], w1.y, g.a[i][3]);
            }
        }
    }
}

// Normal store: C[M,N] row-major, + bias
__global__ __launch_bounds__(256, 2) void k_gemm(const float* __restrict__ A,
                                                 const float* __restrict__ W,
                                                 const float* __restrict__ bias,
                                                 float* __restrict__ C,
                                                 int M, int N, int K) {
    const int bm = blockIdx.y * 128;
    const int bn = blockIdx.x * 128;
    const int tid = threadIdx.x;
    const int tx = tid & 15;
    const int ty = tid >> 4;
    GemmAcc g;
    gemm_core(A, W, K, bm, bn, tid, g);

    float4 b0 = *(const float4*)(bias + bn + tx * 4);
    float4 b1 = *(const float4*)(bias + bn + 64 + tx * 4);
#pragma unroll
    for (int i = 0; i < 8; i++) {
        int row = bm + ((i < 4) ? (ty * 4 + i) : (64 + ty * 4 + (i - 4)));
        float* Cr = C + (size_t)row * N + bn;
        float2 v00 = u2f(g.a[i][0]), v01 = u2f(g.a[i][1]);
        float2 v10 = u2f(g.a[i][2]), v11 = u2f(g.a[i][3]);
        float4 o0, o1;
        o0.x = v00.x + b0.x; o0.y = v00.y + b0.y;
        o0.z = v01.x + b0.z; o0.w = v01.y + b0.w;
        o1.x = v10.x + b1.x; o1.y = v10.y + b1.y;
        o1.z = v11.x + b1.z; o1.w = v11.y + b1.w;
        *(float4*)(Cr + tx * 4) = o0;
        *(float4*)(Cr + 64 + tx * 4) = o1;
    }
}

// Transposed store: Ct[N][M] = (A*W^T + bias)^T  (for xgT)
__global__ __launch_bounds__(256, 2) void k_gemm_t(const float* __restrict__ A,
                                                   const float* __restrict__ W,
                                                   const float* __restrict__ bias,
                                                   float* __restrict__ Ct,
                                                   int M, int N, int K) {
    const int bm = blockIdx.y * 128;
    const int bn = blockIdx.x * 128;
    const int tid = threadIdx.x;
    const int tx = tid & 15;
    const int ty = tid >> 4;
    GemmAcc g;
    gemm_core(A, W, K, bm, bn, tid, g);

    // columns handled by this thread: jj in 0..3 packs 2 cols (x,y)
#pragma unroll
    for (int jj = 0; jj < 4; jj++) {
#pragma unroll
        for (int half = 0; half < 2; half++) {
            int col = bn + ((jj < 2) ? (tx * 4 + jj * 2 + half)
                                     : (64 + tx * 4 + (jj - 2) * 2 + half));
            float bv = __ldg(bias + col);
            float2 r0 = u2f(g.a[0][jj]), r1 = u2f(g.a[1][jj]);
            float2 r2 = u2f(g.a[2][jj]), r3 = u2f(g.a[3][jj]);
            float2 r4 = u2f(g.a[4][jj]), r5 = u2f(g.a[5][jj]);
            float2 r6 = u2f(g.a[6][jj]), r7 = u2f(g.a[7][jj]);
            float4 lo, hi;
            if (half == 0) {
                lo = make_float4(r0.x, r1.x, r2.x, r3.x);
                hi = make_float4(r4.x, r5.x, r6.x, r7.x);
            } else {
                lo = make_float4(r0.y, r1.y, r2.y, r3.y);
                hi = make_float4(r4.y, r5.y, r6.y, r7.y);
            }
            lo.x += bv; lo.y += bv; lo.z += bv; lo.w += bv;
            hi.x += bv; hi.y += bv; hi.z += bv; hi.w += bv;
            *(float4*)(Ct + (size_t)col * M + bm + ty * 4) = lo;
            *(float4*)(Ct + (size_t)col * M + bm + 64 + ty * 4) = hi;
        }
    }
}

// ---------------------------------------------------------------------------
// Host launcher
// ---------------------------------------------------------------------------
extern "C" void kernel_launch(void* const* d_in, const int* in_sizes, int n_in,
                              void* d_out, int out_size) {
    const int* src = (const int*)d_in[0];
    const int* tgt = (const int*)d_in[1];
    const float* semb = (const float*)d_in[2];
    const float* temb = (const float*)d_in[3];
    const float* eWih = (const float*)d_in[4];   // [2,2,1024,512]
    const float* eWhh = (const float*)d_in[5];   // [2,2,1024,256]
    const float* ebih = (const float*)d_in[6];   // [2,2,1024]
    const float* ebhh = (const float*)d_in[7];   // [2,2,1024]
    const float* dWih = (const float*)d_in[8];   // [2,2048,512]
    const float* dWhh = (const float*)d_in[9];   // [2,2048,512]
    const float* dbih = (const float*)d_in[10];  // [2,2048]
    const float* dbhh = (const float*)d_in[11];  // [2,2048]
    const float* linW = (const float*)d_in[12];  // [32000,512]
    const float* linb = (const float*)d_in[13];  // [32000]
    float* out = (float*)d_out;

    float *bufA, *bufB, *xgT, *hA, *hB, *cst, *hf, *cf;
    cudaGetSymbolAddress((void**)&bufA, g_bufA);
    cudaGetSymbolAddress((void**)&bufB, g_bufB);
    cudaGetSymbolAddress((void**)&xgT, g_xgT);
    cudaGetSymbolAddress((void**)&hA, g_hA);
    cudaGetSymbolAddress((void**)&hB, g_hB);
    cudaGetSymbolAddress((void**)&cst, g_cst);
    cudaGetSymbolAddress((void**)&hf, g_hfin);
    cudaGetSymbolAddress((void**)&cf, g_cfin);

    // ---- Encoder ----
    k_embed<<<TB, 128>>>(src, semb, bufA);
    for (int l = 0; l < 2; l++) {
        const float* xin = (l == 0) ? bufA : bufB;
        float* yout = (l == 0) ? bufB : bufA;
        k_gemm_t<<<dim3(16, 20), 256>>>(xin, eWih + (size_t)l * 2048 * 512,
                                        ebih + l * 2048, xgT, TB, 2048, 512);
        k_init_enc<<<64, 256>>>(hA, cst);
        for (int t = 0; t < TT; t++) {
            const float4* hin = (const float4*)((t & 1) ? hB : hA);
            float* hout = (t & 1) ? hA : hB;
            k_step<HENC, 2><<<dim3(HENC / 4, 2), 128>>>(
                xgT, eWhh + (size_t)l * 2 * 1024 * 256, ebhh + l * 2048,
                hin, hout, cst, yout,
                hf + l * NB * 512, cf + l * NB * 512, t);
        }
    }

    // ---- Decoder ----
    k_embed<<<TB, 128>>>(tgt, temb, bufA);
    for (int l = 0; l < 2; l++) {
        const float* yin = (l == 0) ? bufA : bufB;
        float* yout = (l == 0) ? bufB : bufA;
        k_gemm_t<<<dim3(16, 20), 256>>>(yin, dWih + (size_t)l * 2048 * 512,
                                        dbih + l * 2048, xgT, TB, 2048, 512);
        k_init_dec<<<64, 256>>>(hA, cst, hf + l * NB * 512, cf + l * NB * 512);
        for (int t = 0; t < TT; t++) {
            const float4* hin = (const float4*)((t & 1) ? hB : hA);
            float* hout = (t & 1) ? hA : hB;
            k_step<HDEC, 1><<<dim3(HDEC / 4, 1), 128>>>(
                xgT, dWhh + (size_t)l * 2048 * 512, dbhh + l * 2048,
                hin, hout, cst, yout, nullptr, nullptr, t);
        }
    }

    // ---- Output projection: logits[2560,32000] ----
    k_gemm<<<dim3(VT / 128, TB / 128), 256>>>(bufA, linW, linb, out, TB, VT, 512);
}

// round 6
// speedup vs baseline: 1.7914x; 1.5729x over previous
#include <cuda_runtime.h>
#include <cuda_bf16.h>
#include <cstdint>

// Problem constants
#define TT 40
#define NB 64            // batch
#define EE 512           // embed
#define HENC 256         // encoder hidden per direction
#define HDEC 512         // decoder hidden
#define TB (TT*NB)       // 2560 rows
#define VT 32000

// ---------------------------------------------------------------------------
// Scratch (static device globals; no allocation allowed)
// ---------------------------------------------------------------------------
__device__ float g_bufA[TB * EE];          // 5.24 MB  ping
__device__ float g_bufB[TB * EE];          // 5.24 MB  pong
__device__ float g_xgT[2048 * TB];         // 21 MB    input gates, TRANSPOSED [gate][row]
__device__ float g_hA[32768];              // h ping, transposed layout (128 KB)
__device__ float g_hB[32768];              // h pong
__device__ float g_cst[65536];             // c state, [dir*HC+u][b] layout
__device__ float g_hfin[2 * NB * 512];     // encoder final h per layer (concat f|b)
__device__ float g_cfin[2 * NB * 512];

// ---------------------------------------------------------------------------
// f32x2 packed-math helpers (Blackwell FFMA2: 2x fp32 FMA throughput,
// only reachable via PTX fma.rn.f32x2; bit-exact IEEE fp32 per lane)
// ---------------------------------------------------------------------------
typedef unsigned long long ull;

__device__ __forceinline__ ull f2u(float x, float y) {
    ull r; asm("mov.b64 %0, {%1, %2};" : "=l"(r) : "f"(x), "f"(y)); return r;
}
__device__ __forceinline__ ull ffma2(ull a, ull b, ull c) {
    ull d; asm("fma.rn.f32x2 %0, %1, %2, %3;" : "=l"(d) : "l"(a), "l"(b), "l"(c)); return d;
}
__device__ __forceinline__ float2 u2f(ull v) {
    float2 r; asm("mov.b64 {%0, %1}, %2;" : "=f"(r.x), "=f"(r.y) : "l"(v)); return r;
}
__device__ __forceinline__ float hsum2(ull v) {
    float2 r = u2f(v); return r.x + r.y;
}
__device__ __forceinline__ float sigf(float x) {
    return 1.0f / (1.0f + __expf(-x));
}

// ---------------------------------------------------------------------------
// Embedding gather
// ---------------------------------------------------------------------------
__global__ __launch_bounds__(128) void k_embed(const int* __restrict__ tok,
                                               const float* __restrict__ emb,
                                               float* __restrict__ out) {
    int i = blockIdx.x;
    int t = tok[i];
    const float4* s = (const float4*)(emb + (size_t)t * EE);
    float4* d = (float4*)(out + (size_t)i * EE);
    d[threadIdx.x] = s[threadIdx.x];
}

// ---------------------------------------------------------------------------
// Init: encoder h/c zeros ; decoder h/c from encoder finals.
// h layout: hT[k4][b] packs h[b][4k4..4k4+3] as float4 (per-dir slab for enc)
// c layout: c[(dir*HC+u)*64 + b]
// ---------------------------------------------------------------------------
__global__ void k_init_enc(float* __restrict__ hA, float* __restrict__ cst) {
    int i = blockIdx.x * blockDim.x + threadIdx.x;
    for (int j = i; j < 32768; j += gridDim.x * blockDim.x) hA[j] = 0.0f;
    for (int j = i; j < 65536; j += gridDim.x * blockDim.x) cst[j] = 0.0f;
}

__global__ void k_init_dec(float* __restrict__ hA, float* __restrict__ cst,
                           const float* __restrict__ hf, const float* __restrict__ cf) {
    int i = blockIdx.x * blockDim.x + threadIdx.x;
    for (int j = i; j < 32768; j += gridDim.x * blockDim.x) {
        int k4 = j >> 8;          // 0..127
        int rem = j & 255;
        int bb = rem >> 2;        // 0..63
        int comp = rem & 3;
        hA[j] = hf[bb * 512 + k4 * 4 + comp];
    }
    for (int j = i; j < 32768; j += gridDim.x * blockDim.x) {
        int u = j >> 6;           // 0..511
        int bb = j & 63;
        cst[j] = cf[bb * 512 + u];
    }
}

// ---------------------------------------------------------------------------
// LSTM single step, issue-rate-oriented:
//  - 256 threads (8 warps), block owns 4 hidden units of one direction
//  - thread (b=tid&31, ks=(tid>>5)&1, ul=tid>>6): all 4 gates of unit u0+ul
//    for batch rows b,b+32 over k-slice [ks*KH, (ks+1)*KH)
//  - Whh slice staged to smem with coalesced loads, read back as LDS.128
//    broadcast (conflict-free)
//  - h read via coalesced LDG from transposed ping-pong buffer
//  - 2-way k-split partials reduced through smem, then 256-thread
//    activation/update phase
// ---------------------------------------------------------------------------
template <int HC, int NDIR>
__global__ __launch_bounds__(256) void k_step(
    const float* __restrict__ xgT,   // [NDIR*4*HC][TB]
    const float* __restrict__ Whh,   // [NDIR*4*HC, HC]
    const float* __restrict__ bhh,   // [NDIR*4*HC]
    const float4* __restrict__ hin,  // transposed, per-dir slabs
    float* __restrict__ hout,
    float* __restrict__ cst,         // [dir*HC+u][64]
    float* __restrict__ y,           // [T*64, NDIR*HC]
    float* __restrict__ hfin, float* __restrict__ cfin,  // enc finals
    int t)
{
    constexpr int K4 = HC / 4;
    constexpr int KH = K4 / 2;
    const int dir = (NDIR == 2) ? blockIdx.y : 0;
    const int td = dir ? (TT - 1 - t) : t;
    const int u0 = blockIdx.x * 4;
    const int tid = threadIdx.x;
    const int b = tid & 31;
    const int ks = (tid >> 5) & 1;
    const int ul = tid >> 6;          // 0..3
    const int xb = dir * 4 * HC;

    __shared__ float4 ws4[16 * K4];   // 16 gate-rows (g*4+unit) of Whh
    __shared__ float red[2][16][64];  // [ks][g*4+ul][batch]

    // Cooperative coalesced staging of the Whh slice
    const float* wbase = Whh + (size_t)dir * 4 * HC * HC;
    for (int i = tid; i < 16 * K4; i += 256) {
        int r = i >> (K4 == 64 ? 6 : 7);      // i / K4
        int k4 = i - r * K4;
        int g = r >> 2, uu = r & 3;
        ws4[i] = ((const float4*)(wbase + (size_t)(g * HC + u0 + uu) * HC))[k4];
    }
    __syncthreads();

    const float4* hrow = hin + dir * (K4 * 64);

    ull a0g0 = 0, a0g1 = 0, a0g2 = 0, a0g3 = 0;   // batch b
    ull a1g0 = 0, a1g1 = 0, a1g2 = 0, a1g3 = 0;   // batch b+32

    const float4* wsu = ws4 + ul * K4;            // rows g*4+ul at offset (g*4+ul)*K4

#pragma unroll 8
    for (int k4 = ks * KH; k4 < ks * KH + KH; k4++) {
        float4 h0 = hrow[k4 * 64 + b];
        float4 h1 = hrow[k4 * 64 + b + 32];
        float4 wv0 = wsu[0 * 4 * K4 + k4];
        float4 wv1 = wsu[1 * 4 * K4 + k4];
        float4 wv2 = wsu[2 * 4 * K4 + k4];
        float4 wv3 = wsu[3 * 4 * K4 + k4];
        ull h0a = f2u(h0.x, h0.y), h0b = f2u(h0.z, h0.w);
        ull h1a = f2u(h1.x, h1.y), h1b = f2u(h1.z, h1.w);
        ull w0a = f2u(wv0.x, wv0.y), w0b = f2u(wv0.z, wv0.w);
        ull w1a = f2u(wv1.x, wv1.y), w1b = f2u(wv1.z, wv1.w);
        ull w2a = f2u(wv2.x, wv2.y), w2b = f2u(wv2.z, wv2.w);
        ull w3a = f2u(wv3.x, wv3.y), w3b = f2u(wv3.z, wv3.w);
        a0g0 = ffma2(h0a, w0a, a0g0); a0g0 = ffma2(h0b, w0b, a0g0);
        a0g1 = ffma2(h0a, w1a, a0g1); a0g1 = ffma2(h0b, w1b, a0g1);
        a0g2 = ffma2(h0a, w2a, a0g2); a0g2 = ffma2(h0b, w2b, a0g2);
        a0g3 = ffma2(h0a, w3a, a0g3); a0g3 = ffma2(h0b, w3b, a0g3);
        a1g0 = ffma2(h1a, w0a, a1g0); a1g0 = ffma2(h1b, w0b, a1g0);
        a1g1 = ffma2(h1a, w1a, a1g1); a1g1 = ffma2(h1b, w1b, a1g1);
        a1g2 = ffma2(h1a, w2a, a1g2); a1g2 = ffma2(h1b, w2b, a1g2);
        a1g3 = ffma2(h1a, w3a, a1g3); a1g3 = ffma2(h1b, w3b, a1g3);
    }

    // k-split partials -> smem
    red[ks][0 * 4 + ul][b] = hsum2(a0g0);
    red[ks][1 * 4 + ul][b] = hsum2(a0g1);
    red[ks][2 * 4 + ul][b] = hsum2(a0g2);
    red[ks][3 * 4 + ul][b] = hsum2(a0g3);
    red[ks][0 * 4 + ul][b + 32] = hsum2(a1g0);
    red[ks][1 * 4 + ul][b + 32] = hsum2(a1g1);
    red[ks][2 * 4 + ul][b + 32] = hsum2(a1g2);
    red[ks][3 * 4 + ul][b + 32] = hsum2(a1g3);
    __syncthreads();

    // Activation / state update: 256 threads = 4 units x 64 rows
    {
        const int bg = tid & 63;
        const int vl = tid >> 6;                 // unit-local
        const int u = u0 + vl;
        float s0 = red[0][0 * 4 + vl][bg] + red[1][0 * 4 + vl][bg];
        float s1 = red[0][1 * 4 + vl][bg] + red[1][1 * 4 + vl][bg];
        float s2 = red[0][2 * 4 + vl][bg] + red[1][2 * 4 + vl][bg];
        float s3 = red[0][3 * 4 + vl][bg] + red[1][3 * 4 + vl][bg];

        const size_t rowoff = (size_t)td * NB;
        float vi = s0 + xgT[(size_t)(xb + 0 * HC + u) * TB + rowoff + bg] + __ldg(bhh + xb + 0 * HC + u);
        float vf = s1 + xgT[(size_t)(xb + 1 * HC + u) * TB + rowoff + bg] + __ldg(bhh + xb + 1 * HC + u);
        float vg = s2 + xgT[(size_t)(xb + 2 * HC + u) * TB + rowoff + bg] + __ldg(bhh + xb + 2 * HC + u);
        float vo = s3 + xgT[(size_t)(xb + 3 * HC + u) * TB + rowoff + bg] + __ldg(bhh + xb + 3 * HC + u);

        float* crow = cst + (size_t)(dir * HC + u) * 64;
        float cn = sigf(vf) * crow[bg] + sigf(vi) * tanhf(vg);
        float hn = sigf(vo) * tanhf(cn);
        crow[bg] = cn;

        float* hd = hout + dir * (K4 * 256);
        hd[(u >> 2) * 256 + bg * 4 + (u & 3)] = hn;
        y[(size_t)(td * NB + bg) * (NDIR * HC) + dir * HC + u] = hn;
        if (NDIR == 2 && t == TT - 1) {
            hfin[bg * (2 * HC) + dir * HC + u] = hn;
            cfin[bg * (2 * HC) + dir * HC + u] = cn;
        }
    }
}

// ---------------------------------------------------------------------------
// Shared GEMM core: acc[8][4] (f32x2) of C[M,N] = A[M,K]*W[N,K]^T
// 128x128 tile, BK=8, 256 threads, 8x8 micro-tile, register prefetch.
// ---------------------------------------------------------------------------
struct GemmAcc { ull a[8][4]; };

__device__ __forceinline__ void gemm_core(const float* __restrict__ A,
                                          const float* __restrict__ W,
                                          int K, int bm, int bn,
                                          int tid, GemmAcc& g) {
    __shared__ float As[8][128];
    __shared__ float Ws[8][128];
    const int lr = tid >> 1;
    const int lc = (tid & 1) << 2;
    const int tx = tid & 15;
    const int ty = tid >> 4;

    const float* Ap = A + (size_t)(bm + lr) * K + lc;
    const float* Wp = W + (size_t)(bn + lr) * K + lc;

#pragma unroll
    for (int i = 0; i < 8; i++)
#pragma unroll
        for (int j = 0; j < 4; j++) g.a[i][j] = 0;

    float4 a = *(const float4*)Ap;
    float4 w = *(const float4*)Wp;

    for (int k0 = 0; k0 < K; k0 += 8) {
        __syncthreads();
        As[lc + 0][lr] = a.x; As[lc + 1][lr] = a.y;
        As[lc + 2][lr] = a.z; As[lc + 3][lr] = a.w;
        Ws[lc + 0][lr] = w.x; Ws[lc + 1][lr] = w.y;
        Ws[lc + 2][lr] = w.z; Ws[lc + 3][lr] = w.w;
        __syncthreads();
        if (k0 + 8 < K) {
            a = *(const float4*)(Ap + k0 + 8);
            w = *(const float4*)(Wp + k0 + 8);
        }
#pragma unroll
        for (int kk = 0; kk < 8; kk++) {
            float4 a0 = *(const float4*)&As[kk][ty * 4];
            float4 a1 = *(const float4*)&As[kk][64 + ty * 4];
            ulonglong2 w0 = *(const ulonglong2*)&Ws[kk][tx * 4];
            ulonglong2 w1 = *(const ulonglong2*)&Ws[kk][64 + tx * 4];
            ull ab[8];
            ab[0] = f2u(a0.x, a0.x); ab[1] = f2u(a0.y, a0.y);
            ab[2] = f2u(a0.z, a0.z); ab[3] = f2u(a0.w, a0.w);
            ab[4] = f2u(a1.x, a1.x); ab[5] = f2u(a1.y, a1.y);
            ab[6] = f2u(a1.z, a1.z); ab[7] = f2u(a1.w, a1.w);
#pragma unroll
            for (int i = 0; i < 8; i++) {
                g.a[i][0] = ffma2(ab[i], w0.x, g.a[i][0]);
                g.a[i][1] = ffma2(ab[i], w0.y, g.a[i][1]);
                g.a[i][2] = ffma2(ab[i], w1.x, g.a[i][2]);
                g.a[i][3] = ffma2(ab[i], w1.y, g.a[i][3]);
            }
        }
    }
}

// Normal store: C[M,N] row-major, + bias
__global__ __launch_bounds__(256, 2) void k_gemm(const float* __restrict__ A,
                                                 const float* __restrict__ W,
                                                 const float* __restrict__ bias,
                                                 float* __restrict__ C,
                                                 int M, int N, int K) {
    const int bm = blockIdx.y * 128;
    const int bn = blockIdx.x * 128;
    const int tid = threadIdx.x;
    const int tx = tid & 15;
    const int ty = tid >> 4;
    GemmAcc g;
    gemm_core(A, W, K, bm, bn, tid, g);

    float4 b0 = *(const float4*)(bias + bn + tx * 4);
    float4 b1 = *(const float4*)(bias + bn + 64 + tx * 4);
#pragma unroll
    for (int i = 0; i < 8; i++) {
        int row = bm + ((i < 4) ? (ty * 4 + i) : (64 + ty * 4 + (i - 4)));
        float* Cr = C + (size_t)row * N + bn;
        float2 v00 = u2f(g.a[i][0]), v01 = u2f(g.a[i][1]);
        float2 v10 = u2f(g.a[i][2]), v11 = u2f(g.a[i][3]);
        float4 o0, o1;
        o0.x = v00.x + b0.x; o0.y = v00.y + b0.y;
        o0.z = v01.x + b0.z; o0.w = v01.y + b0.w;
        o1.x = v10.x + b1.x; o1.y = v10.y + b1.y;
        o1.z = v11.x + b1.z; o1.w = v11.y + b1.w;
        *(float4*)(Cr + tx * 4) = o0;
        *(float4*)(Cr + 64 + tx * 4) = o1;
    }
}

// Transposed store: Ct[N][M] = (A*W^T + bias)^T  (for xgT)
__global__ __launch_bounds__(256, 2) void k_gemm_t(const float* __restrict__ A,
                                                   const float* __restrict__ W,
                                                   const float* __restrict__ bias,
                                                   float* __restrict__ Ct,
                                                   int M, int N, int K) {
    const int bm = blockIdx.y * 128;
    const int bn = blockIdx.x * 128;
    const int tid = threadIdx.x;
    const int tx = tid & 15;
    const int ty = tid >> 4;
    GemmAcc g;
    gemm_core(A, W, K, bm, bn, tid, g);

#pragma unroll
    for (int jj = 0; jj < 4; jj++) {
#pragma unroll
        for (int half = 0; half < 2; half++) {
            int col = bn + ((jj < 2) ? (tx * 4 + jj * 2 + half)
                                     : (64 + tx * 4 + (jj - 2) * 2 + half));
            float bv = __ldg(bias + col);
            float2 r0 = u2f(g.a[0][jj]), r1 = u2f(g.a[1][jj]);
            float2 r2 = u2f(g.a[2][jj]), r3 = u2f(g.a[3][jj]);
            float2 r4 = u2f(g.a[4][jj]), r5 = u2f(g.a[5][jj]);
            float2 r6 = u2f(g.a[6][jj]), r7 = u2f(g.a[7][jj]);
            float4 lo, hi;
            if (half == 0) {
                lo = make_float4(r0.x, r1.x, r2.x, r3.x);
                hi = make_float4(r4.x, r5.x, r6.x, r7.x);
            } else {
                lo = make_float4(r0.y, r1.y, r2.y, r3.y);
                hi = make_float4(r4.y, r5.y, r6.y, r7.y);
            }
            lo.x += bv; lo.y += bv; lo.z += bv; lo.w += bv;
            hi.x += bv; hi.y += bv; hi.z += bv; hi.w += bv;
            *(float4*)(Ct + (size_t)col * M + bm + ty * 4) = lo;
            *(float4*)(Ct + (size_t)col * M + bm + 64 + ty * 4) = hi;
        }
    }
}

// ---------------------------------------------------------------------------
// Host launcher
// ---------------------------------------------------------------------------
extern "C" void kernel_launch(void* const* d_in, const int* in_sizes, int n_in,
                              void* d_out, int out_size) {
    const int* src = (const int*)d_in[0];
    const int* tgt = (const int*)d_in[1];
    const float* semb = (const float*)d_in[2];
    const float* temb = (const float*)d_in[3];
    const float* eWih = (const float*)d_in[4];   // [2,2,1024,512]
    const float* eWhh = (const float*)d_in[5];   // [2,2,1024,256]
    const float* ebih = (const float*)d_in[6];   // [2,2,1024]
    const float* ebhh = (const float*)d_in[7];   // [2,2,1024]
    const float* dWih = (const float*)d_in[8];   // [2,2048,512]
    const float* dWhh = (const float*)d_in[9];   // [2,2048,512]
    const float* dbih = (const float*)d_in[10];  // [2,2048]
    const float* dbhh = (const float*)d_in[11];  // [2,2048]
    const float* linW = (const float*)d_in[12];  // [32000,512]
    const float* linb = (const float*)d_in[13];  // [32000]
    float* out = (float*)d_out;

    float *bufA, *bufB, *xgT, *hA, *hB, *cst, *hf, *cf;
    cudaGetSymbolAddress((void**)&bufA, g_bufA);
    cudaGetSymbolAddress((void**)&bufB, g_bufB);
    cudaGetSymbolAddress((void**)&xgT, g_xgT);
    cudaGetSymbolAddress((void**)&hA, g_hA);
    cudaGetSymbolAddress((void**)&hB, g_hB);
    cudaGetSymbolAddress((void**)&cst, g_cst);
    cudaGetSymbolAddress((void**)&hf, g_hfin);
    cudaGetSymbolAddress((void**)&cf, g_cfin);

    // ---- Encoder ----
    k_embed<<<TB, 128>>>(src, semb, bufA);
    for (int l = 0; l < 2; l++) {
        const float* xin = (l == 0) ? bufA : bufB;
        float* yout = (l == 0) ? bufB : bufA;
        k_gemm_t<<<dim3(16, 20), 256>>>(xin, eWih + (size_t)l * 2048 * 512,
                                        ebih + l * 2048, xgT, TB, 2048, 512);
        k_init_enc<<<64, 256>>>(hA, cst);
        for (int t = 0; t < TT; t++) {
            const float4* hin = (const float4*)((t & 1) ? hB : hA);
            float* hout = (t & 1) ? hA : hB;
            k_step<HENC, 2><<<dim3(HENC / 4, 2), 256>>>(
                xgT, eWhh + (size_t)l * 2 * 1024 * 256, ebhh + l * 2048,
                hin, hout, cst, yout,
                hf + l * NB * 512, cf + l * NB * 512, t);
        }
    }

    // ---- Decoder ----
    k_embed<<<TB, 128>>>(tgt, temb, bufA);
    for (int l = 0; l < 2; l++) {
        const float* yin = (l == 0) ? bufA : bufB;
        float* yout = (l == 0) ? bufB : bufA;
        k_gemm_t<<<dim3(16, 20), 256>>>(yin, dWih + (size_t)l * 2048 * 512,
                                        dbih + l * 2048, xgT, TB, 2048, 512);
        k_init_dec<<<64, 256>>>(hA, cst, hf + l * NB * 512, cf + l * NB * 512);
        for (int t = 0; t < TT; t++) {
            const float4* hin = (const float4*)((t & 1) ? hB : hA);
            float* hout = (t & 1) ? hA : hB;
            k_step<HDEC, 1><<<dim3(HDEC / 4, 1), 256>>>(
                xgT, dWhh + (size_t)l * 2048 * 512, dbhh + l * 2048,
                hin, hout, cst, yout, nullptr, nullptr, t);
        }
    }

    // ---- Output projection: logits[2560,32000] ----
    k_gemm<<<dim3(VT / 128, TB / 128), 256>>>(bufA, linW, linb, out, TB, VT, 512);
}

// round 8
// speedup vs baseline: 2.4912x; 1.3907x over previous
#include <cuda_runtime.h>
#include <cuda_bf16.h>
#include <cstdint>

// Problem constants
#define TT 40
#define NB 64            // batch
#define EE 512           // embed
#define HENC 256         // encoder hidden per direction
#define HDEC 512         // decoder hidden
#define TB (TT*NB)       // 2560 rows
#define VT 32000

// ---------------------------------------------------------------------------
// Scratch (static device globals; no allocation allowed)
// ---------------------------------------------------------------------------
__device__ float g_bufA[TB * EE];          // 5.24 MB  ping
__device__ float g_bufB[TB * EE];          // 5.24 MB  pong
__device__ float g_xgT[2048 * TB];         // 21 MB    input gates, TRANSPOSED [gate][row]
__device__ float g_hA[32768];              // h ping, transposed layout (128 KB)
__device__ float g_hB[32768];              // h pong
__device__ float g_cst[65536];             // c state, [dir*HC+u][b] layout
__device__ float g_hfin[2 * NB * 512];     // encoder final h per layer (concat f|b)
__device__ float g_cfin[2 * NB * 512];

// ---------------------------------------------------------------------------
// f32x2 packed-math helpers (Blackwell FFMA2: 2x fp32 FMA throughput,
// only reachable via PTX fma.rn.f32x2; bit-exact IEEE fp32 per lane)
// ---------------------------------------------------------------------------
typedef unsigned long long ull;

__device__ __forceinline__ ull f2u(float x, float y) {
    ull r; asm("mov.b64 %0, {%1, %2};" : "=l"(r) : "f"(x), "f"(y)); return r;
}
__device__ __forceinline__ ull ffma2(ull a, ull b, ull c) {
    ull d; asm("fma.rn.f32x2 %0, %1, %2, %3;" : "=l"(d) : "l"(a), "l"(b), "l"(c)); return d;
}
__device__ __forceinline__ float2 u2f(ull v) {
    float2 r; asm("mov.b64 {%0, %1}, %2;" : "=f"(r.x), "=f"(r.y) : "l"(v)); return r;
}
__device__ __forceinline__ float hsum2(ull v) {
    float2 r = u2f(v); return r.x + r.y;
}
__device__ __forceinline__ float sigf(float x) {
    return 1.0f / (1.0f + __expf(-x));
}

// ---------------------------------------------------------------------------
// Embedding gather
// ---------------------------------------------------------------------------
__global__ __launch_bounds__(128) void k_embed(const int* __restrict__ tok,
                                               const float* __restrict__ emb,
                                               float* __restrict__ out) {
    int i = blockIdx.x;
    int t = tok[i];
    const float4* s = (const float4*)(emb + (size_t)t * EE);
    float4* d = (float4*)(out + (size_t)i * EE);
    d[threadIdx.x] = s[threadIdx.x];
}

// ---------------------------------------------------------------------------
// Init: encoder h/c zeros ; decoder h/c from encoder finals.
// h layout: hT[k4][b] packs h[b][4k4..4k4+3] as float4 (per-dir slab for enc)
// c layout: c[(dir*HC+u)*64 + b]
// ---------------------------------------------------------------------------
__global__ void k_init_enc(float* __restrict__ hA, float* __restrict__ cst) {
    int i = blockIdx.x * blockDim.x + threadIdx.x;
    for (int j = i; j < 32768; j += gridDim.x * blockDim.x) hA[j] = 0.0f;
    for (int j = i; j < 65536; j += gridDim.x * blockDim.x) cst[j] = 0.0f;
}

__global__ void k_init_dec(float* __restrict__ hA, float* __restrict__ cst,
                           const float* __restrict__ hf, const float* __restrict__ cf) {
    int i = blockIdx.x * blockDim.x + threadIdx.x;
    for (int j = i; j < 32768; j += gridDim.x * blockDim.x) {
        int k4 = j >> 8;          // 0..127
        int rem = j & 255;
        int bb = rem >> 2;        // 0..63
        int comp = rem & 3;
        hA[j] = hf[bb * 512 + k4 * 4 + comp];
    }
    for (int j = i; j < 32768; j += gridDim.x * blockDim.x) {
        int u = j >> 6;           // 0..511
        int bb = j & 63;
        cst[j] = cf[bb * 512 + u];
    }
}

// ---------------------------------------------------------------------------
// LSTM single step, latency-hiding-oriented:
//  - block owns 2 hidden units of one direction; 256 threads (8 warps)
//  - grid: enc (HC/2, 2) = 256 blocks; dec (HC/2, 1) = 256 blocks
//    -> ~1.7 blocks/SM, double R6's warp-level latency hiding
//  - thread (b=tid&31, ks=(tid>>5)&3, ul=tid>>7): all 4 gates of unit u0+ul
//    for batch rows b,b+32 over quarter k-slice ks (KH = K4/4 iterations)
//  - Whh slice (8 gate-rows) staged to smem coalesced; LDS.128 broadcast
//  - activation-phase operands (xgT: DRAM; c; biases) PREFETCHED at kernel
//    entry so their latency hides under staging + main loop
//  - 4-way k-split partials reduced through smem; 128 threads do activation
// ---------------------------------------------------------------------------
template <int HC, int NDIR>
__global__ __launch_bounds__(256) void k_step(
    const float* __restrict__ xgT,   // [NDIR*4*HC][TB]
    const float* __restrict__ Whh,   // [NDIR*4*HC, HC]
    const float* __restrict__ bhh,   // [NDIR*4*HC]
    const float4* __restrict__ hin,  // transposed, per-dir slabs
    float* __restrict__ hout,
    float* __restrict__ cst,         // [dir*HC+u][64]
    float* __restrict__ y,           // [T*64, NDIR*HC]
    float* __restrict__ hfin, float* __restrict__ cfin,  // enc finals
    int t)
{
    constexpr int K4 = HC / 4;       // float4 groups in K
    constexpr int KH = K4 / 4;       // per-thread k iterations (enc 16, dec 32)
    const int dir = (NDIR == 2) ? blockIdx.y : 0;
    const int td = dir ? (TT - 1 - t) : t;
    const int u0 = blockIdx.x * 2;
    const int tid = threadIdx.x;
    const int b = tid & 31;
    const int ks = (tid >> 5) & 3;   // 0..3
    const int ul = tid >> 7;         // 0..1
    const int xb = dir * 4 * HC;

    __shared__ float4 ws4[8 * K4];   // 8 gate-rows (g*2+unit) of Whh
    __shared__ float red[4][8][64];  // [ks][g*2+ul][batch]

    // ---- prefetch activation operands (independent of h) ----
    const int bg = tid & 63;
    const int vl = (tid >> 6) & 1;
    const int ua = u0 + vl;
    float xv0 = 0, xv1 = 0, xv2 = 0, xv3 = 0;
    float bh0 = 0, bh1 = 0, bh2 = 0, bh3 = 0;
    float cold = 0;
    if (tid < 128) {
        const size_t rowoff = (size_t)td * NB + bg;
        xv0 = __ldg(xgT + (size_t)(xb + 0 * HC + ua) * TB + rowoff);
        xv1 = __ldg(xgT + (size_t)(xb + 1 * HC + ua) * TB + rowoff);
        xv2 = __ldg(xgT + (size_t)(xb + 2 * HC + ua) * TB + rowoff);
        xv3 = __ldg(xgT + (size_t)(xb + 3 * HC + ua) * TB + rowoff);
        bh0 = __ldg(bhh + xb + 0 * HC + ua);
        bh1 = __ldg(bhh + xb + 1 * HC + ua);
        bh2 = __ldg(bhh + xb + 2 * HC + ua);
        bh3 = __ldg(bhh + xb + 3 * HC + ua);
        cold = cst[(size_t)(dir * HC + ua) * 64 + bg];
    }

    // ---- stage Whh slice (8 rows: gate g, unit u0+uu), coalesced ----
    const float* wbase = Whh + (size_t)dir * 4 * HC * HC;
    for (int i = tid; i < 8 * K4; i += 256) {
        int r = i >> (K4 == 64 ? 6 : 7);      // i / K4
        int k4 = i - r * K4;
        int g = r >> 1, uu = r & 1;
        ws4[i] = ((const float4*)(wbase + (size_t)(g * HC + u0 + uu) * HC))[k4];
    }
    __syncthreads();

    // ---- main phase: gate partials over quarter k-slice ----
    const float4* hrow = hin + dir * (K4 * 64);
    const float4* wsu = ws4 + ul * K4;        // rows g*2+ul at (g*2+ul)*K4

    ull a0g0 = 0, a0g1 = 0, a0g2 = 0, a0g3 = 0;   // batch b
    ull a1g0 = 0, a1g1 = 0, a1g2 = 0, a1g3 = 0;   // batch b+32

#pragma unroll 8
    for (int k4 = ks * KH; k4 < ks * KH + KH; k4++) {
        float4 h0 = hrow[k4 * 64 + b];
        float4 h1 = hrow[k4 * 64 + b + 32];
        float4 wv0 = wsu[0 * 2 * K4 + k4];
        float4 wv1 = wsu[1 * 2 * K4 + k4];
        float4 wv2 = wsu[2 * 2 * K4 + k4];
        float4 wv3 = wsu[3 * 2 * K4 + k4];
        ull h0a = f2u(h0.x, h0.y), h0b = f2u(h0.z, h0.w);
        ull h1a = f2u(h1.x, h1.y), h1b = f2u(h1.z, h1.w);
        ull w0a = f2u(wv0.x, wv0.y), w0b = f2u(wv0.z, wv0.w);
        ull w1a = f2u(wv1.x, wv1.y), w1b = f2u(wv1.z, wv1.w);
        ull w2a = f2u(wv2.x, wv2.y), w2b = f2u(wv2.z, wv2.w);
        ull w3a = f2u(wv3.x, wv3.y), w3b = f2u(wv3.z, wv3.w);
        a0g0 = ffma2(h0a, w0a, a0g0); a0g0 = ffma2(h0b, w0b, a0g0);
        a0g1 = ffma2(h0a, w1a, a0g1); a0g1 = ffma2(h0b, w1b, a0g1);
        a0g2 = ffma2(h0a, w2a, a0g2); a0g2 = ffma2(h0b, w2b, a0g2);
        a0g3 = ffma2(h0a, w3a, a0g3); a0g3 = ffma2(h0b, w3b, a0g3);
        a1g0 = ffma2(h1a, w0a, a1g0); a1g0 = ffma2(h1b, w0b, a1g0);
        a1g1 = ffma2(h1a, w1a, a1g1); a1g1 = ffma2(h1b, w1b, a1g1);
        a1g2 = ffma2(h1a, w2a, a1g2); a1g2 = ffma2(h1b, w2b, a1g2);
        a1g3 = ffma2(h1a, w3a, a1g3); a1g3 = ffma2(h1b, w3b, a1g3);
    }

    red[ks][0 * 2 + ul][b] = hsum2(a0g0);
    red[ks][1 * 2 + ul][b] = hsum2(a0g1);
    red[ks][2 * 2 + ul][b] = hsum2(a0g2);
    red[ks][3 * 2 + ul][b] = hsum2(a0g3);
    red[ks][0 * 2 + ul][b + 32] = hsum2(a1g0);
    red[ks][1 * 2 + ul][b + 32] = hsum2(a1g1);
    red[ks][2 * 2 + ul][b + 32] = hsum2(a1g2);
    red[ks][3 * 2 + ul][b + 32] = hsum2(a1g3);
    __syncthreads();

    // ---- activation phase: 128 threads = 2 units x 64 rows ----
    if (tid < 128) {
        float s0 = red[0][0 * 2 + vl][bg] + red[1][0 * 2 + vl][bg]
                 + red[2][0 * 2 + vl][bg] + red[3][0 * 2 + vl][bg];
        float s1 = red[0][1 * 2 + vl][bg] + red[1][1 * 2 + vl][bg]
                 + red[2][1 * 2 + vl][bg] + red[3][1 * 2 + vl][bg];
        float s2 = red[0][2 * 2 + vl][bg] + red[1][2 * 2 + vl][bg]
                 + red[2][2 * 2 + vl][bg] + red[3][2 * 2 + vl][bg];
        float s3 = red[0][3 * 2 + vl][bg] + red[1][3 * 2 + vl][bg]
                 + red[2][3 * 2 + vl][bg] + red[3][3 * 2 + vl][bg];

        float vi = s0 + xv0 + bh0;
        float vf = s1 + xv1 + bh1;
        float vg = s2 + xv2 + bh2;
        float vo = s3 + xv3 + bh3;

        float cn = sigf(vf) * cold + sigf(vi) * tanhf(vg);
        float hn = sigf(vo) * tanhf(cn);
        cst[(size_t)(dir * HC + ua) * 64 + bg] = cn;

        float* hd = hout + dir * (K4 * 256);
        hd[(ua >> 2) * 256 + bg * 4 + (ua & 3)] = hn;
        y[(size_t)(td * NB + bg) * (NDIR * HC) + dir * HC + ua] = hn;
        if (NDIR == 2 && t == TT - 1) {
            hfin[bg * (2 * HC) + dir * HC + ua] = hn;
            cfin[bg * (2 * HC) + dir * HC + ua] = cn;
        }
    }
}

// ---------------------------------------------------------------------------
// Shared GEMM core: acc[8][4] (f32x2) of C[M,N] = A[M,K]*W[N,K]^T
// 128x128 tile, BK=8, 256 threads, 8x8 micro-tile, register prefetch.
// ---------------------------------------------------------------------------
struct GemmAcc { ull a[8][4]; };

__device__ __forceinline__ void gemm_core(const float* __restrict__ A,
                                          const float* __restrict__ W,
                                          int K, int bm, int bn,
                                          int tid, GemmAcc& g) {
    __shared__ float As[8][128];
    __shared__ float Ws[8][128];
    const int lr = tid >> 1;
    const int lc = (tid & 1) << 2;
    const int tx = tid & 15;
    const int ty = tid >> 4;

    const float* Ap = A + (size_t)(bm + lr) * K + lc;
    const float* Wp = W + (size_t)(bn + lr) * K + lc;

#pragma unroll
    for (int i = 0; i < 8; i++)
#pragma unroll
        for (int j = 0; j < 4; j++) g.a[i][j] = 0;

    float4 a = *(const float4*)Ap;
    float4 w = *(const float4*)Wp;

    for (int k0 = 0; k0 < K; k0 += 8) {
        __syncthreads();
        As[lc + 0][lr] = a.x; As[lc + 1][lr] = a.y;
        As[lc + 2][lr] = a.z; As[lc + 3][lr] = a.w;
        Ws[lc + 0][lr] = w.x; Ws[lc + 1][lr] = w.y;
        Ws[lc + 2][lr] = w.z; Ws[lc + 3][lr] = w.w;
        __syncthreads();
        if (k0 + 8 < K) {
            a = *(const float4*)(Ap + k0 + 8);
            w = *(const float4*)(Wp + k0 + 8);
        }
#pragma unroll
        for (int kk = 0; kk < 8; kk++) {
            float4 a0 = *(const float4*)&As[kk][ty * 4];
            float4 a1 = *(const float4*)&As[kk][64 + ty * 4];
            ulonglong2 w0 = *(const ulonglong2*)&Ws[kk][tx * 4];
            ulonglong2 w1 = *(const ulonglong2*)&Ws[kk][64 + tx * 4];
            ull ab[8];
            ab[0] = f2u(a0.x, a0.x); ab[1] = f2u(a0.y, a0.y);
            ab[2] = f2u(a0.z, a0.z); ab[3] = f2u(a0.w, a0.w);
            ab[4] = f2u(a1.x, a1.x); ab[5] = f2u(a1.y, a1.y);
            ab[6] = f2u(a1.z, a1.z); ab[7] = f2u(a1.w, a1.w);
#pragma unroll
            for (int i = 0; i < 8; i++) {
                g.a[i][0] = ffma2(ab[i], w0.x, g.a[i][0]);
                g.a[i][1] = ffma2(ab[i], w0.y, g.a[i][1]);
                g.a[i][2] = ffma2(ab[i], w1.x, g.a[i][2]);
                g.a[i][3] = ffma2(ab[i], w1.y, g.a[i][3]);
            }
        }
    }
}

// Normal store: C[M,N] row-major, + bias
__global__ __launch_bounds__(256, 2) void k_gemm(const float* __restrict__ A,
                                                 const float* __restrict__ W,
                                                 const float* __restrict__ bias,
                                                 float* __restrict__ C,
                                                 int M, int N, int K) {
    const int bm = blockIdx.y * 128;
    const int bn = blockIdx.x * 128;
    const int tid = threadIdx.x;
    const int tx = tid & 15;
    const int ty = tid >> 4;
    GemmAcc g;
    gemm_core(A, W, K, bm, bn, tid, g);

    float4 b0 = *(const float4*)(bias + bn + tx * 4);
    float4 b1 = *(const float4*)(bias + bn + 64 + tx * 4);
#pragma unroll
    for (int i = 0; i < 8; i++) {
        int row = bm + ((i < 4) ? (ty * 4 + i) : (64 + ty * 4 + (i - 4)));
        float* Cr = C + (size_t)row * N + bn;
        float2 v00 = u2f(g.a[i][0]), v01 = u2f(g.a[i][1]);
        float2 v10 = u2f(g.a[i][2]), v11 = u2f(g.a[i][3]);
        float4 o0, o1;
        o0.x = v00.x + b0.x; o0.y = v00.y + b0.y;
        o0.z = v01.x + b0.z; o0.w = v01.y + b0.w;
        o1.x = v10.x + b1.x; o1.y = v10.y + b1.y;
        o1.z = v11.x + b1.z; o1.w = v11.y + b1.w;
        *(float4*)(Cr + tx * 4) = o0;
        *(float4*)(Cr + 64 + tx * 4) = o1;
    }
}

// Transposed store: Ct[N][M] = (A*W^T + bias)^T  (for xgT)
__global__ __launch_bounds__(256, 2) void k_gemm_t(const float* __restrict__ A,
                                                   const float* __restrict__ W,
                                                   const float* __restrict__ bias,
                                                   float* __restrict__ Ct,
                                                   int M, int N, int K) {
    const int bm = blockIdx.y * 128;
    const int bn = blockIdx.x * 128;
    const int tid = threadIdx.x;
    const int tx = tid & 15;
    const int ty = tid >> 4;
    GemmAcc g;
    gemm_core(A, W, K, bm, bn, tid, g);

#pragma unroll
    for (int jj = 0; jj < 4; jj++) {
#pragma unroll
        for (int half = 0; half < 2; half++) {
            int col = bn + ((jj < 2) ? (tx * 4 + jj * 2 + half)
                                     : (64 + tx * 4 + (jj - 2) * 2 + half));
            float bv = __ldg(bias + col);
            float2 r0 = u2f(g.a[0][jj]), r1 = u2f(g.a[1][jj]);
            float2 r2 = u2f(g.a[2][jj]), r3 = u2f(g.a[3][jj]);
            float2 r4 = u2f(g.a[4][jj]), r5 = u2f(g.a[5][jj]);
            float2 r6 = u2f(g.a[6][jj]), r7 = u2f(g.a[7][jj]);
            float4 lo, hi;
            if (half == 0) {
                lo = make_float4(r0.x, r1.x, r2.x, r3.x);
                hi = make_float4(r4.x, r5.x, r6.x, r7.x);
            } else {
                lo = make_float4(r0.y, r1.y, r2.y, r3.y);
                hi = make_float4(r4.y, r5.y, r6.y, r7.y);
            }
            lo.x += bv; lo.y += bv; lo.z += bv; lo.w += bv;
            hi.x += bv; hi.y += bv; hi.z += bv; hi.w += bv;
            *(float4*)(Ct + (size_t)col * M + bm + ty * 4) = lo;
            *(float4*)(Ct + (size_t)col * M + bm + 64 + ty * 4) = hi;
        }
    }
}

// ---------------------------------------------------------------------------
// Host launcher
// ---------------------------------------------------------------------------
extern "C" void kernel_launch(void* const* d_in, const int* in_sizes, int n_in,
                              void* d_out, int out_size) {
    const int* src = (const int*)d_in[0];
    const int* tgt = (const int*)d_in[1];
    const float* semb = (const float*)d_in[2];
    const float* temb = (const float*)d_in[3];
    const float* eWih = (const float*)d_in[4];   // [2,2,1024,512]
    const float* eWhh = (const float*)d_in[5];   // [2,2,1024,256]
    const float* ebih = (const float*)d_in[6];   // [2,2,1024]
    const float* ebhh = (const float*)d_in[7];   // [2,2,1024]
    const float* dWih = (const float*)d_in[8];   // [2,2048,512]
    const float* dWhh = (const float*)d_in[9];   // [2,2048,512]
    const float* dbih = (const float*)d_in[10];  // [2,2048]
    const float* dbhh = (const float*)d_in[11];  // [2,2048]
    const float* linW = (const float*)d_in[12];  // [32000,512]
    const float* linb = (const float*)d_in[13];  // [32000]
    float* out = (float*)d_out;

    float *bufA, *bufB, *xgT, *hA, *hB, *cst, *hf, *cf;
    cudaGetSymbolAddress((void**)&bufA, g_bufA);
    cudaGetSymbolAddress((void**)&bufB, g_bufB);
    cudaGetSymbolAddress((void**)&xgT, g_xgT);
    cudaGetSymbolAddress((void**)&hA, g_hA);
    cudaGetSymbolAddress((void**)&hB, g_hB);
    cudaGetSymbolAddress((void**)&cst, g_cst);
    cudaGetSymbolAddress((void**)&hf, g_hfin);
    cudaGetSymbolAddress((void**)&cf, g_cfin);

    // ---- Encoder ----
    k_embed<<<TB, 128>>>(src, semb, bufA);
    for (int l = 0; l < 2; l++) {
        const float* xin = (l == 0) ? bufA : bufB;
        float* yout = (l == 0) ? bufB : bufA;
        k_gemm_t<<<dim3(16, 20), 256>>>(xin, eWih + (size_t)l * 2048 * 512,
                                        ebih + l * 2048, xgT, TB, 2048, 512);
        k_init_enc<<<64, 256>>>(hA, cst);
        for (int t = 0; t < TT; t++) {
            const float4* hin = (const float4*)((t & 1) ? hB : hA);
            float* hout = (t & 1) ? hA : hB;
            k_step<HENC, 2><<<dim3(HENC / 2, 2), 256>>>(
                xgT, eWhh + (size_t)l * 2 * 1024 * 256, ebhh + l * 2048,
                hin, hout, cst, yout,
                hf + l * NB * 512, cf + l * NB * 512, t);
        }
    }

    // ---- Decoder ----
    k_embed<<<TB, 128>>>(tgt, temb, bufA);
    for (int l = 0; l < 2; l++) {
        const float* yin = (l == 0) ? bufA : bufB;
        float* yout = (l == 0) ? bufB : bufA;
        k_gemm_t<<<dim3(16, 20), 256>>>(yin, dWih + (size_t)l * 2048 * 512,
                                        dbih + l * 2048, xgT, TB, 2048, 512);
        k_init_dec<<<64, 256>>>(hA, cst, hf + l * NB * 512, cf + l * NB * 512);
        for (int t = 0; t < TT; t++) {
            const float4* hin = (const float4*)((t & 1) ? hB : hA);
            float* hout = (t & 1) ? hA : hB;
            k_step<HDEC, 1><<<dim3(HDEC / 2, 1), 256>>>(
                xgT, dWhh + (size_t)l * 2048 * 512, dbhh + l * 2048,
                hin, hout, cst, yout, nullptr, nullptr, t);
        }
    }

    // ---- Output projection: logits[2560,32000] ----
    k_gemm<<<dim3(VT / 128, TB / 128), 256>>>(bufA, linW, linb, out, TB, VT, 512);
}